// round 2
// baseline (speedup 1.0000x reference)
#include <cuda_runtime.h>
#include <math.h>

// ---------------------------------------------------------------------------
// Mamba block forward, fp32.
// B=2, T=2048, d_model=1024, d_inner=2048, d_state=16, dt_rank=64, d_conv=4
// Pipeline:
//   G1: xz = x @ in_proj_w^T                     [4096, 4096]
//   conv+silu: xc (depthwise causal 4-tap)       [4096, 2048]
//   G2: x_dbl = xc @ x_proj_w^T                  [4096, 96]   (dt_lo|B|C)
//   G3: dt = softplus(dt_lo @ dt_proj_w^T + b)   [4096, 2048]
//   scan: y = selective_scan(...) * silu(z)      [4096, 2048]
//   G4: out = y @ out_proj_w^T                   [4096, 1024]
// ---------------------------------------------------------------------------

#define D_MODEL  1024
#define D_STATE  16
#define D_CONV   4
#define D_INNER  2048
#define DT_RANK  64
#define BATCH    2
#define SEQ      2048
#define M_TOK    (BATCH * SEQ)   // 4096

// Scratch (device globals — allocation-free per harness rules)
__device__ float g_xz  [(size_t)M_TOK * 2 * D_INNER];  // 64 MB  (xi | z)
__device__ float g_xc  [(size_t)M_TOK * D_INNER];      // 32 MB
__device__ float g_xdbl[(size_t)M_TOK * 96];           // 1.5 MB (dt_lo|B|C)
__device__ float g_dt  [(size_t)M_TOK * D_INNER];      // 32 MB
__device__ float g_y   [(size_t)M_TOK * D_INNER];      // 32 MB

// ---------------------------------------------------------------------------
// Generic SGEMM: C[m,n] = sum_k A[m*lda+k] * B[n*ldb+k]   (both K-contiguous)
// Assumes M % BM == 0, N % BN == 0, K % BK == 0, lda/ldb % 4 == 0 (true for
// every call here, so no bounds predication).
// EPI: 0 = store, 1 = softplus(acc + bias[n])
// ---------------------------------------------------------------------------
template<int BM, int BN, int BK, int TM, int TN, int EPI>
__global__ void __launch_bounds__((BM/TM)*(BN/TN))
sgemm_tn(const float* __restrict__ A, int lda,
         const float* __restrict__ Bm, int ldb,
         float* __restrict__ C, int ldc, int K,
         const float* __restrict__ bias)
{
    constexpr int THREADS = (BM/TM)*(BN/TN);
    constexpr int KV = BK / 4;            // float4 columns per k-tile
    __shared__ float As[BK][BM];
    __shared__ float Bs[BK][BN];

    const int tid = threadIdx.x;
    const int txc = BN / TN;
    const int tx  = tid % txc;
    const int ty  = tid / txc;
    const long m0 = (long)blockIdx.y * BM;
    const long n0 = (long)blockIdx.x * BN;

    float acc[TM][TN];
#pragma unroll
    for (int i = 0; i < TM; i++)
#pragma unroll
        for (int j = 0; j < TN; j++) acc[i][j] = 0.f;

    for (int kk = 0; kk < K; kk += BK) {
        // load A tile (BM x BK), store k-major for conflict-lite compute reads
#pragma unroll
        for (int e = tid; e < BM * KV; e += THREADS) {
            int row = e / KV;
            int k4  = e % KV;
            float4 v = *(const float4*)(A + (m0 + row) * lda + kk + k4 * 4);
            As[k4*4+0][row] = v.x; As[k4*4+1][row] = v.y;
            As[k4*4+2][row] = v.z; As[k4*4+3][row] = v.w;
        }
#pragma unroll
        for (int e = tid; e < BN * KV; e += THREADS) {
            int row = e / KV;
            int k4  = e % KV;
            float4 v = *(const float4*)(Bm + (n0 + row) * ldb + kk + k4 * 4);
            Bs[k4*4+0][row] = v.x; Bs[k4*4+1][row] = v.y;
            Bs[k4*4+2][row] = v.z; Bs[k4*4+3][row] = v.w;
        }
        __syncthreads();

#pragma unroll
        for (int k = 0; k < BK; k++) {
            float ra[TM], rb[TN];
#pragma unroll
            for (int i = 0; i < TM; i++) ra[i] = As[k][ty * TM + i];
#pragma unroll
            for (int j = 0; j < TN; j++) rb[j] = Bs[k][tx * TN + j];
#pragma unroll
            for (int i = 0; i < TM; i++)
#pragma unroll
                for (int j = 0; j < TN; j++)
                    acc[i][j] = fmaf(ra[i], rb[j], acc[i][j]);
        }
        __syncthreads();
    }

#pragma unroll
    for (int i = 0; i < TM; i++) {
        long m = m0 + ty * TM + i;
#pragma unroll
        for (int j = 0; j < TN; j++) {
            long n = n0 + tx * TN + j;
            float v = acc[i][j];
            if (EPI == 1) {
                v += bias[n];
                v = (v > 20.f) ? v : log1pf(expf(v));  // softplus
            }
            C[m * ldc + n] = v;
        }
    }
}

// ---------------------------------------------------------------------------
// Depthwise causal conv (4-tap) + SiLU.  xi = g_xz[:, 0:2048] -> g_xc
// ---------------------------------------------------------------------------
__global__ void conv_silu_kernel(const float* __restrict__ conv_w,
                                 const float* __restrict__ conv_b)
{
    long idx = (long)blockIdx.x * blockDim.x + threadIdx.x;
    if (idx >= (long)M_TOK * D_INNER) return;
    int d = (int)(idx & (D_INNER - 1));
    long m = idx >> 11;             // / D_INNER
    int t = (int)(m & (SEQ - 1));
    long row0 = m - t;              // first token of this batch

    float acc = conv_b[d];
    const float* w = conv_w + d * 4;
#pragma unroll
    for (int j = 0; j < D_CONV; j++) {
        int tt = t - (D_CONV - 1) + j;
        if (tt >= 0)
            acc = fmaf(g_xz[(row0 + tt) * (2 * D_INNER) + d], w[j], acc);
    }
    // silu
    float s = __fdividef(1.f, 1.f + __expf(-acc));
    g_xc[m * D_INNER + d] = acc * s;
}

// ---------------------------------------------------------------------------
// Selective scan. One thread per (channel, state): 4096 channels x 16 states.
// Warp = 2 channels; 16-lane shfl_xor reduce for y_t. Fuses + Dp*x and
// * silu(z) epilogue. Writes g_y.
// ---------------------------------------------------------------------------
__global__ void __launch_bounds__(256)
scan_kernel(const float* __restrict__ A_log,
            const float* __restrict__ Dp)
{
    int tid = blockIdx.x * 256 + threadIdx.x;
    int s = tid & 15;
    int c = tid >> 4;               // channel 0..4095
    int d = c & (D_INNER - 1);
    int b = c >> 11;

    const float a  = -__expf(A_log[d * D_STATE + s]);
    const float Dv = Dp[d];
    float h = 0.f;

    const float* dt_p = g_dt   + (long)b * SEQ * D_INNER + d;
    const float* xc_p = g_xc   + (long)b * SEQ * D_INNER + d;
    const float* z_p  = g_xz   + (long)b * SEQ * (2 * D_INNER) + D_INNER + d;
    const float* bc_p = g_xdbl + (long)b * SEQ * 96 + DT_RANK + s;
    float*       y_p  = g_y    + (long)b * SEQ * D_INNER + d;

    for (int t = 0; t < SEQ; t++) {
        float dt = __ldg(dt_p);
        float xv = __ldg(xc_p);
        float Bv = __ldg(bc_p);
        float Cv = __ldg(bc_p + D_STATE);

        float dA = __expf(dt * a);
        h = fmaf(dA, h, dt * Bv * xv);

        float p = h * Cv;
        p += __shfl_xor_sync(0xffffffffu, p, 8);
        p += __shfl_xor_sync(0xffffffffu, p, 4);
        p += __shfl_xor_sync(0xffffffffu, p, 2);
        p += __shfl_xor_sync(0xffffffffu, p, 1);

        if (s == 0) {
            float z  = __ldg(z_p);
            float yv = fmaf(Dv, xv, p);
            float sg = __fdividef(1.f, 1.f + __expf(-z));
            *y_p = yv * z * sg;
        }
        dt_p += D_INNER; xc_p += D_INNER; z_p += 2 * D_INNER;
        bc_p += 96;      y_p  += D_INNER;
    }
}

// ---------------------------------------------------------------------------
extern "C" void kernel_launch(void* const* d_in, const int* in_sizes, int n_in,
                              void* d_out, int out_size)
{
    const float* x          = (const float*)d_in[0];
    const float* in_proj_w  = (const float*)d_in[1];
    const float* conv_w     = (const float*)d_in[2];
    const float* conv_b     = (const float*)d_in[3];
    const float* x_proj_w   = (const float*)d_in[4];
    const float* dt_proj_w  = (const float*)d_in[5];
    const float* dt_proj_b  = (const float*)d_in[6];
    const float* A_log      = (const float*)d_in[7];
    const float* Dp         = (const float*)d_in[8];
    const float* out_proj_w = (const float*)d_in[9];
    float* out = (float*)d_out;

    float *xz, *xc, *xdbl, *dt, *y;
    cudaGetSymbolAddress((void**)&xz,   g_xz);
    cudaGetSymbolAddress((void**)&xc,   g_xc);
    cudaGetSymbolAddress((void**)&xdbl, g_xdbl);
    cudaGetSymbolAddress((void**)&dt,   g_dt);
    cudaGetSymbolAddress((void**)&y,    g_y);

    // G1: xz = x @ in_proj_w^T   M=4096 N=4096 K=1024
    sgemm_tn<128,128,16,8,8,0><<<dim3(4096/128, M_TOK/128), 256>>>(
        x, D_MODEL, in_proj_w, D_MODEL, xz, 2*D_INNER, D_MODEL, nullptr);

    // conv + silu
    {
        long n = (long)M_TOK * D_INNER;
        conv_silu_kernel<<<(int)((n + 255) / 256), 256>>>(conv_w, conv_b);
    }

    // G2: x_dbl = xc @ x_proj_w^T   M=4096 N=96 K=2048  (small-N config)
    sgemm_tn<64,32,32,4,4,0><<<dim3(96/32, M_TOK/64), 128>>>(
        xc, D_INNER, x_proj_w, D_INNER, xdbl, 96, D_INNER, nullptr);

    // G3: dt = softplus(dt_lo @ dt_proj_w^T + b)   M=4096 N=2048 K=64
    sgemm_tn<128,128,16,8,8,1><<<dim3(D_INNER/128, M_TOK/128), 256>>>(
        xdbl, 96, dt_proj_w, DT_RANK, dt, D_INNER, DT_RANK, dt_proj_b);

    // selective scan (+ Dp*x, * silu(z))
    scan_kernel<<<(M_TOK * D_STATE) / 256, 256>>>(A_log, Dp);

    // G4: out = y @ out_proj_w^T   M=4096 N=1024 K=2048
    sgemm_tn<128,128,16,8,8,0><<<dim3(D_MODEL/128, M_TOK/128), 256>>>(
        y, D_INNER, out_proj_w, D_INNER, out, D_MODEL, D_INNER, nullptr);
}

// round 6
// speedup vs baseline: 1.4295x; 1.4295x over previous
#include <cuda_runtime.h>
#include <cuda_bf16.h>
#include <cuda_pipeline.h>
#include <math.h>
#include <stdint.h>

// ---------------------------------------------------------------------------
// Mamba block forward. GEMMs: bf16x3 split-precision on mma.sync tensor cores.
// Conservative build: static smem <=48KB (no cudaFuncSetAttribute), cp.async
// via __pipeline intrinsics, no lambdas, no TMA/mbarrier/driver API.
// B=2, T=2048, d_model=1024, d_inner=2048, d_state=16, dt_rank=64, d_conv=4
// ---------------------------------------------------------------------------

#define D_MODEL  1024
#define D_STATE  16
#define D_CONV   4
#define D_INNER  2048
#define DT_RANK  64
#define BATCH    2
#define SEQ      2048
#define M_TOK    (BATCH * SEQ)   // 4096

typedef __nv_bfloat16 bf16;

// fp32 scratch
__device__ float g_xz  [(size_t)M_TOK * 2 * D_INNER];
__device__ float g_xc  [(size_t)M_TOK * D_INNER];
__device__ float g_xdbl[(size_t)M_TOK * 96];
__device__ float g_dt  [(size_t)M_TOK * D_INNER];

// bf16 hi/lo operand scratch
__device__ bf16 g_xh [(size_t)M_TOK * D_MODEL],  g_xl [(size_t)M_TOK * D_MODEL];
__device__ bf16 g_w1h[(size_t)2*D_INNER*D_MODEL],g_w1l[(size_t)2*D_INNER*D_MODEL];
__device__ bf16 g_xch[(size_t)M_TOK * D_INNER],  g_xcl[(size_t)M_TOK * D_INNER];
__device__ bf16 g_xwh[(size_t)96 * D_INNER],     g_xwl[(size_t)96 * D_INNER];
__device__ bf16 g_dth[(size_t)M_TOK * DT_RANK],  g_dtl[(size_t)M_TOK * DT_RANK];
__device__ bf16 g_dwh[(size_t)D_INNER * DT_RANK],g_dwl[(size_t)D_INNER * DT_RANK];
__device__ bf16 g_yh [(size_t)M_TOK * D_INNER],  g_yl [(size_t)M_TOK * D_INNER];
__device__ bf16 g_owh[(size_t)D_MODEL * D_INNER],g_owl[(size_t)D_MODEL * D_INNER];

// ---------------------------------------------------------------------------
// PTX helpers (sm_80 baseline)
// ---------------------------------------------------------------------------
__device__ __forceinline__ uint32_t smem_u32(const void* p) {
    uint32_t a;
    asm("{ .reg .u64 t; cvta.to.shared.u64 t, %1; cvt.u32.u64 %0, t; }"
        : "=r"(a) : "l"(p));
    return a;
}

#define LDSM4(r0, r1, r2, r3, addr) \
    asm volatile("ldmatrix.sync.aligned.m8n8.x4.shared.b16 {%0,%1,%2,%3}, [%4];" \
        : "=r"(r0), "=r"(r1), "=r"(r2), "=r"(r3) : "r"(addr))

#define MMA_BF16(d, a, b) \
    asm volatile("mma.sync.aligned.m16n8k16.row.col.f32.bf16.bf16.f32 " \
        "{%0,%1,%2,%3}, {%4,%5,%6,%7}, {%8,%9}, {%0,%1,%2,%3};" \
        : "+f"((d)[0]), "+f"((d)[1]), "+f"((d)[2]), "+f"((d)[3]) \
        : "r"((a)[0]), "r"((a)[1]), "r"((a)[2]), "r"((a)[3]), \
          "r"((b)[0]), "r"((b)[1]))

// ---------------------------------------------------------------------------
// Stage loader: one k16 slab of Ah/Al/Bh/Bl into stride-24 smem rows.
// Row = 16 valid bf16 (2 x 16B chunks) + 8 bf16 pad -> conflict-free ldmatrix.
// ---------------------------------------------------------------------------
template<int BM, int BN>
__device__ __forceinline__ void stage_load(
    bf16* sb, const bf16* aH, const bf16* aL, int lda,
    const bf16* bH, const bf16* bL, int ldb, int koff, int tid)
{
    constexpr int TOT = (BM + BN) * 2;
#pragma unroll
    for (int e = tid; e < TOT; e += 256) {
        if (e < BM * 2) {
            const int r = e >> 1, c = e & 1;
            const long so = (long)r * lda + koff + c * 8;
            bf16* d = sb + r * 24 + c * 8;
            __pipeline_memcpy_async(d,           aH + so, 16);
            __pipeline_memcpy_async(d + BM * 24, aL + so, 16);
        } else {
            const int eb = e - BM * 2;
            const int r = eb >> 1, c = eb & 1;
            const long so = (long)r * ldb + koff + c * 8;
            bf16* d = sb + 2 * BM * 24 + r * 24 + c * 8;
            __pipeline_memcpy_async(d,           bH + so, 16);
            __pipeline_memcpy_async(d + BN * 24, bL + so, 16);
        }
    }
    __pipeline_commit();
}

// ---------------------------------------------------------------------------
// Tensor-core bf16x3 GEMM:  C[m,n] = sum_k A[m,k]*B[n,k]
// D = Ah*Bh + Al*Bh + Ah*Bl  (fp32 accum, mma.sync m16n8k16)
// BK=16, double-buffered. 256 threads = 8 warps, warp tile WM x WN.
// EPI: 0 = store, 1 = softplus(acc + bias[n]).
// ---------------------------------------------------------------------------
template<int BM, int BN, int WM, int WN, int EPI>
__global__ void __launch_bounds__(256)
gemm_mma(const bf16* __restrict__ Ah, const bf16* __restrict__ Al, int lda,
         const bf16* __restrict__ Bh, const bf16* __restrict__ Bl, int ldb,
         float* __restrict__ C, int ldc, int K,
         const float* __restrict__ bias)
{
    constexpr int STAGE_E = (2 * BM + 2 * BN) * 24;      // elements per stage
    constexpr int WARPS_N = BN / WN;
    constexpr int MA = WM / 16;
    constexpr int NA = WN / 8;                           // even

    __shared__ bf16 smem[2 * STAGE_E];                   // <= 48KB

    const int tid = threadIdx.x, wid = tid >> 5, lane = tid & 31;
    const int wm = wid / WARPS_N, wn = wid % WARPS_N;
    const int m0 = blockIdx.y * BM;
    const int n0 = blockIdx.x * BN;
    const int KT = K >> 4;

    const bf16* aH = Ah + (long)m0 * lda;
    const bf16* aL = Al + (long)m0 * lda;
    const bf16* bH = Bh + (long)n0 * ldb;
    const bf16* bL = Bl + (long)n0 * ldb;

    float acc[MA][NA][4];
#pragma unroll
    for (int i = 0; i < MA; i++)
#pragma unroll
        for (int j = 0; j < NA; j++)
#pragma unroll
            for (int e = 0; e < 4; e++) acc[i][j][e] = 0.f;

    // ldmatrix lane addressing (A row-major [m][k]; B [n][k] -> mma .col)
    const int a_row  = wm * WM + (lane & 15);            // + ma*16
    const int a_csel = lane >> 4;                        // 16B chunk
    const int bg     = lane >> 3;
    const int b_row  = wn * WN + (lane & 7) + ((bg >> 1) << 3);  // + p*16
    const int b_csel = bg & 1;

    const uint32_t s0 = smem_u32(smem);

    stage_load<BM, BN>(smem, aH, aL, lda, bH, bL, ldb, 0, tid);

    for (int kt = 0; kt < KT; ++kt) {
        if (kt + 1 < KT) {
            stage_load<BM, BN>(smem + ((kt + 1) & 1) * STAGE_E,
                               aH, aL, lda, bH, bL, ldb, (kt + 1) * 16, tid);
            __pipeline_wait_prior(1);
        } else {
            __pipeline_wait_prior(0);
        }
        __syncthreads();

        const uint32_t base = s0 + (kt & 1) * (STAGE_E * 2);   // bytes
        const uint32_t pAh = base;
        const uint32_t pAl = base + BM * 48;
        const uint32_t pBh = base + 2 * BM * 48;
        const uint32_t pBl = pBh + BN * 48;

        uint32_t ar[MA][4], alr[MA][4], br[NA][2], blr[NA][2];
#pragma unroll
        for (int ma = 0; ma < MA; ++ma) {
            const uint32_t off = (a_row + ma * 16) * 48 + a_csel * 16;
            LDSM4(ar[ma][0],  ar[ma][1],  ar[ma][2],  ar[ma][3],  pAh + off);
            LDSM4(alr[ma][0], alr[ma][1], alr[ma][2], alr[ma][3], pAl + off);
        }
#pragma unroll
        for (int p = 0; p < NA / 2; ++p) {
            const uint32_t off = (b_row + p * 16) * 48 + b_csel * 16;
            LDSM4(br[2*p][0],  br[2*p][1],  br[2*p+1][0],  br[2*p+1][1],  pBh + off);
            LDSM4(blr[2*p][0], blr[2*p][1], blr[2*p+1][0], blr[2*p+1][1], pBl + off);
        }
#pragma unroll
        for (int ma = 0; ma < MA; ++ma)
#pragma unroll
            for (int na = 0; na < NA; ++na) {
                MMA_BF16(acc[ma][na], ar[ma],  br[na]);
                MMA_BF16(acc[ma][na], alr[ma], br[na]);
                MMA_BF16(acc[ma][na], ar[ma],  blr[na]);
            }
        __syncthreads();
    }

    // epilogue from registers: (row = lane>>2, col = 2*(lane&3)) and row+8
    const int er = lane >> 2, ec = (lane & 3) * 2;
#pragma unroll
    for (int ma = 0; ma < MA; ++ma) {
#pragma unroll
        for (int na = 0; na < NA; ++na) {
            const int m = m0 + wm * WM + ma * 16 + er;
            const int n = n0 + wn * WN + na * 8 + ec;
            float2 v0 = {acc[ma][na][0], acc[ma][na][1]};
            float2 v1 = {acc[ma][na][2], acc[ma][na][3]};
            if (EPI == 1) {
                const float b0 = bias[n], b1 = bias[n + 1];
                v0.x += b0; v0.y += b1; v1.x += b0; v1.y += b1;
                v0.x = (v0.x > 20.f) ? v0.x : log1pf(__expf(v0.x));
                v0.y = (v0.y > 20.f) ? v0.y : log1pf(__expf(v0.y));
                v1.x = (v1.x > 20.f) ? v1.x : log1pf(__expf(v1.x));
                v1.y = (v1.y > 20.f) ? v1.y : log1pf(__expf(v1.y));
            }
            *(float2*)(C + (long)m * ldc + n)       = v0;
            *(float2*)(C + (long)(m + 8) * ldc + n) = v1;
        }
    }
}

// ---------------------------------------------------------------------------
// fp32 -> bf16 hi/lo split (cols power of two; src row stride ld)
// ---------------------------------------------------------------------------
__global__ void cvt_split(const float* __restrict__ src, int ld, int lc,
                          bf16* __restrict__ hi, bf16* __restrict__ lo, long total)
{
    long i = (long)blockIdx.x * blockDim.x + threadIdx.x;
    if (i >= total) return;
    long r = i >> lc;
    int c = (int)(i & ((1 << lc) - 1));
    float v = src[r * ld + c];
    bf16 h = __float2bfloat16(v);
    hi[i] = h;
    lo[i] = __float2bfloat16(v - __bfloat162float(h));
}

// ---------------------------------------------------------------------------
// Depthwise causal conv (4-tap) + SiLU + hi/lo emit
// ---------------------------------------------------------------------------
__global__ void conv_silu_kernel(const float* __restrict__ conv_w,
                                 const float* __restrict__ conv_b)
{
    long idx = (long)blockIdx.x * blockDim.x + threadIdx.x;
    if (idx >= (long)M_TOK * D_INNER) return;
    int d = (int)(idx & (D_INNER - 1));
    long m = idx >> 11;
    int t = (int)(m & (SEQ - 1));
    long row0 = m - t;

    float acc = conv_b[d];
    const float* w = conv_w + d * 4;
#pragma unroll
    for (int j = 0; j < D_CONV; j++) {
        int tt = t - (D_CONV - 1) + j;
        if (tt >= 0)
            acc = fmaf(g_xz[(row0 + tt) * (2 * D_INNER) + d], w[j], acc);
    }
    float s = __fdividef(1.f, 1.f + __expf(-acc));
    float v = acc * s;
    long o = m * D_INNER + d;
    g_xc[o] = v;
    bf16 h = __float2bfloat16(v);
    g_xch[o] = h;
    g_xcl[o] = __float2bfloat16(v - __bfloat162float(h));
}

// ---------------------------------------------------------------------------
// Selective scan; one thread per (channel,state). Emits y hi/lo for G4.
// ---------------------------------------------------------------------------
__global__ void __launch_bounds__(256)
scan_kernel(const float* __restrict__ A_log, const float* __restrict__ Dp)
{
    int tid = blockIdx.x * 256 + threadIdx.x;
    int s = tid & 15;
    int c = tid >> 4;
    int d = c & (D_INNER - 1);
    int b = c >> 11;

    const float a  = -__expf(A_log[d * D_STATE + s]);
    const float Dv = Dp[d];
    float h = 0.f;

    const float* dt_p = g_dt   + (long)b * SEQ * D_INNER + d;
    const float* xc_p = g_xc   + (long)b * SEQ * D_INNER + d;
    const float* z_p  = g_xz   + (long)b * SEQ * (2 * D_INNER) + D_INNER + d;
    const float* bc_p = g_xdbl + (long)b * SEQ * 96 + DT_RANK + s;
    long yo = (long)b * SEQ * D_INNER + d;

    for (int t = 0; t < SEQ; t++) {
        float dt = __ldg(dt_p);
        float xv = __ldg(xc_p);
        float Bv = __ldg(bc_p);
        float Cv = __ldg(bc_p + D_STATE);

        float dA = __expf(dt * a);
        h = fmaf(dA, h, dt * Bv * xv);

        float p = h * Cv;
        p += __shfl_xor_sync(0xffffffffu, p, 8);
        p += __shfl_xor_sync(0xffffffffu, p, 4);
        p += __shfl_xor_sync(0xffffffffu, p, 2);
        p += __shfl_xor_sync(0xffffffffu, p, 1);

        if (s == 0) {
            float z  = __ldg(z_p);
            float yv = fmaf(Dv, xv, p);
            float sg = __fdividef(1.f, 1.f + __expf(-z));
            float out = yv * z * sg;
            bf16 hh = __float2bfloat16(out);
            g_yh[yo] = hh;
            g_yl[yo] = __float2bfloat16(out - __bfloat162float(hh));
        }
        dt_p += D_INNER; xc_p += D_INNER; z_p += 2 * D_INNER;
        bc_p += 96;      yo   += D_INNER;
    }
}

// ---------------------------------------------------------------------------
// Host side
// ---------------------------------------------------------------------------
extern "C" void kernel_launch(void* const* d_in, const int* in_sizes, int n_in,
                              void* d_out, int out_size)
{
    const float* x          = (const float*)d_in[0];
    const float* in_proj_w  = (const float*)d_in[1];
    const float* conv_w     = (const float*)d_in[2];
    const float* conv_b     = (const float*)d_in[3];
    const float* x_proj_w   = (const float*)d_in[4];
    const float* dt_proj_w  = (const float*)d_in[5];
    const float* dt_proj_b  = (const float*)d_in[6];
    const float* A_log      = (const float*)d_in[7];
    const float* Dp         = (const float*)d_in[8];
    const float* out_proj_w = (const float*)d_in[9];
    float* out = (float*)d_out;

    float *xz, *xc, *xdbl, *dt;
    cudaGetSymbolAddress((void**)&xz,   g_xz);
    cudaGetSymbolAddress((void**)&xc,   g_xc);
    cudaGetSymbolAddress((void**)&xdbl, g_xdbl);
    cudaGetSymbolAddress((void**)&dt,   g_dt);
    bf16 *xh,*xl,*w1h,*w1l,*xch,*xcl,*xwh,*xwl,*dth,*dtl,*dwh,*dwl,*yh,*yl,*owh,*owl;
    cudaGetSymbolAddress((void**)&xh,  g_xh);  cudaGetSymbolAddress((void**)&xl,  g_xl);
    cudaGetSymbolAddress((void**)&w1h, g_w1h); cudaGetSymbolAddress((void**)&w1l, g_w1l);
    cudaGetSymbolAddress((void**)&xch, g_xch); cudaGetSymbolAddress((void**)&xcl, g_xcl);
    cudaGetSymbolAddress((void**)&xwh, g_xwh); cudaGetSymbolAddress((void**)&xwl, g_xwl);
    cudaGetSymbolAddress((void**)&dth, g_dth); cudaGetSymbolAddress((void**)&dtl, g_dtl);
    cudaGetSymbolAddress((void**)&dwh, g_dwh); cudaGetSymbolAddress((void**)&dwl, g_dwl);
    cudaGetSymbolAddress((void**)&yh,  g_yh);  cudaGetSymbolAddress((void**)&yl,  g_yl);
    cudaGetSymbolAddress((void**)&owh, g_owh); cudaGetSymbolAddress((void**)&owl, g_owl);

    // ---- conversions (weights + x) ----
    {
        long n;
        n = (long)M_TOK * D_MODEL;
        cvt_split<<<(int)((n+255)/256),256>>>(x, D_MODEL, 10, xh, xl, n);
        n = (long)2*D_INNER * D_MODEL;
        cvt_split<<<(int)((n+255)/256),256>>>(in_proj_w, D_MODEL, 10, w1h, w1l, n);
        n = (long)96 * D_INNER;
        cvt_split<<<(int)((n+255)/256),256>>>(x_proj_w, D_INNER, 11, xwh, xwl, n);
        n = (long)D_INNER * DT_RANK;
        cvt_split<<<(int)((n+255)/256),256>>>(dt_proj_w, DT_RANK, 6, dwh, dwl, n);
        n = (long)D_MODEL * D_INNER;
        cvt_split<<<(int)((n+255)/256),256>>>(out_proj_w, D_INNER, 11, owh, owl, n);
    }

    // G1: xz = x @ in_proj_w^T  [4096, 4096], K=1024
    gemm_mma<128,128,32,64,0><<<dim3(32, 32), 256>>>(
        xh, xl, D_MODEL, w1h, w1l, D_MODEL, xz, 2*D_INNER, D_MODEL, nullptr);

    // conv + silu (+ hi/lo)
    {
        long n = (long)M_TOK * D_INNER;
        conv_silu_kernel<<<(int)((n + 255) / 256), 256>>>(conv_w, conv_b);
    }

    // G2: xdbl = xc @ x_proj_w^T  [4096, 96], K=2048
    gemm_mma<64,96,16,48,0><<<dim3(1, 64), 256>>>(
        xch, xcl, D_INNER, xwh, xwl, D_INNER, xdbl, 96, D_INNER, nullptr);

    // split dt_lo part of xdbl
    {
        long n = (long)M_TOK * DT_RANK;
        cvt_split<<<(int)((n+255)/256),256>>>(xdbl, 96, 6, dth, dtl, n);
    }

    // G3: dt = softplus(dt_lo @ dt_proj_w^T + b)  [4096, 2048], K=64
    gemm_mma<128,128,32,64,1><<<dim3(16, 32), 256>>>(
        dth, dtl, DT_RANK, dwh, dwl, DT_RANK, dt, D_INNER, DT_RANK, dt_proj_b);

    // selective scan
    scan_kernel<<<(M_TOK * D_STATE) / 256, 256>>>(A_log, Dp);

    // G4: out = y @ out_proj_w^T  [4096, 1024], K=2048
    gemm_mma<128,128,32,64,0><<<dim3(8, 32), 256>>>(
        yh, yl, D_INNER, owh, owl, D_INNER, out, D_MODEL, D_INNER, nullptr);
}